// round 7
// baseline (speedup 1.0000x reference)
#include <cuda_runtime.h>
#include <math.h>
#include <float.h>
#include <stdint.h>

#define HID 128
#define MAX_NODES 50000
#define MAX_EDGES 800000

// ------------------------- scratch (static, no allocs) -------------------------
__device__ float g_A[MAX_NODES * HID];     // z @ Wd
__device__ float g_B[MAX_NODES * HID];     // z @ Ws
__device__ float g_R[MAX_NODES * HID];     // z @ W1a
__device__ float g_agg[MAX_NODES * HID];
__device__ int   g_deg[MAX_NODES];
__device__ int   g_off[MAX_NODES + 1];
__device__ int   g_cur[MAX_NODES];
__device__ int   g_csr[MAX_EDGES];

// ------------------------- tf32 helpers (sm_80+ baseline PTX only) -------------------------
__device__ __forceinline__ uint32_t f2tf(float f) {
    uint32_t u;
    asm("cvt.rna.tf32.f32 %0, %1;" : "=r"(u) : "f"(f));
    return u;
}

__device__ __forceinline__ void mma_tf32(float* c, const uint32_t* a, uint32_t b0, uint32_t b1) {
    asm volatile(
        "mma.sync.aligned.m16n8k8.row.col.f32.tf32.tf32.f32 "
        "{%0,%1,%2,%3}, {%4,%5,%6,%7}, {%8,%9}, {%0,%1,%2,%3};"
        : "+f"(c[0]), "+f"(c[1]), "+f"(c[2]), "+f"(c[3])
        : "r"(a[0]), "r"(a[1]), "r"(a[2]), "r"(a[3]), "r"(b0), "r"(b1));
}

// tiling: CTA = 256 thr = 8 warps (4M x 2N), tile 128(M) x 128(N)
#define PAF 132    // full-A / hid pitch (132 % 32 == 4 -> frag loads conflict-free)
#define PAC 68     // chunk-A pitch (68 % 32 == 4)
#define PB  136    // B pitch, k-major (136 % 32 == 8 -> frag loads conflict-free)

// ------------------------- compute core: 8 k8-steps over one 64-K chunk -------------------------
__device__ __forceinline__ void mma_chunk(
    float acc[2][8][4], const uint32_t* __restrict__ Asm, int apitch, int acolBase,
    const uint32_t* __restrict__ Bsm, int wm, int wn, int g, int tg)
{
#pragma unroll
    for (int kk = 0; kk < 64; kk += 8) {
        uint32_t a[2][4];
#pragma unroll
        for (int mt = 0; mt < 2; mt++) {
            const uint32_t* ap = Asm + (wm + mt * 16 + g) * apitch + acolBase + kk + tg;
            a[mt][0] = ap[0];
            a[mt][1] = ap[8 * apitch];
            a[mt][2] = ap[4];
            a[mt][3] = ap[8 * apitch + 4];
        }
#pragma unroll
        for (int nt = 0; nt < 8; nt++) {
            const uint32_t b0 = Bsm[(kk + tg) * PB + wn + nt * 8 + g];
            const uint32_t b1 = Bsm[(kk + tg + 4) * PB + wn + nt * 8 + g];
            mma_tf32(acc[0][nt], a[0], b0, b1);
            mma_tf32(acc[1][nt], a[1], b0, b1);
        }
    }
}

// ------------------------- gemm2: load z tile once, emit g_A = z@Wd, g_B = z@Ws -------------------------
#define GEMM2_SMEM ((128 * PAF + 64 * PB) * 4)   // 102400 B -> 2 CTA/SM

__global__ __launch_bounds__(256, 2) void gemm2_kernel(
    const float* __restrict__ z, const float* __restrict__ Wm, int M)
{
    extern __shared__ uint32_t sm[];
    uint32_t* As = sm;                  // [128][PAF] full K=128
    uint32_t* Bs = sm + 128 * PAF;      // [64][PB] one K-chunk

    const int tid  = threadIdx.x;
    const int wid  = tid >> 5;
    const int lane = tid & 31;
    const int g    = lane >> 2;
    const int tg   = lane & 3;
    const int wm   = (wid & 3) << 5;
    const int wn   = (wid >> 2) << 6;
    const int rowBase = blockIdx.x * 128;

    // load full A tile (128 x 128), cvt tf32
#pragma unroll
    for (int it = 0; it < 16; it++) {
        const int i = it * 256 + tid;
        const int row = i >> 5;
        const int c4  = (i & 31) << 2;
        const int gr = rowBase + row;
        float4 v = make_float4(0.f, 0.f, 0.f, 0.f);
        if (gr < M) v = *(const float4*)(z + (size_t)gr * HID + c4);
        uint32_t* p = As + row * PAF + c4;
        p[0] = f2tf(v.x); p[1] = f2tf(v.y); p[2] = f2tf(v.z); p[3] = f2tf(v.w);
    }

    for (int w = 0; w < 2; w++) {
        const float* W = Wm + (size_t)w * 128 * HID;
        float acc[2][8][4];
#pragma unroll
        for (int mt = 0; mt < 2; mt++)
#pragma unroll
            for (int nt = 0; nt < 8; nt++)
#pragma unroll
                for (int i = 0; i < 4; i++) acc[mt][nt][i] = 0.f;

        for (int chunk = 0; chunk < 2; chunk++) {
#pragma unroll
            for (int it = 0; it < 8; it++) {
                const int i = it * 256 + tid;
                const int k  = i >> 5;
                const int n4 = (i & 31) << 2;
                const float4 v = *(const float4*)(W + (size_t)(chunk * 64 + k) * HID + n4);
                uint32_t* p = Bs + k * PB + n4;
                p[0] = f2tf(v.x); p[1] = f2tf(v.y); p[2] = f2tf(v.z); p[3] = f2tf(v.w);
            }
            __syncthreads();
            mma_chunk(acc, As, PAF, chunk * 64, Bs, wm, wn, g, tg);
            __syncthreads();
        }

        float* C = w ? g_B : g_A;
#pragma unroll
        for (int mt = 0; mt < 2; mt++) {
            const int r0 = rowBase + wm + mt * 16 + g;
            const int r1 = r0 + 8;
#pragma unroll
            for (int nt = 0; nt < 8; nt++) {
                const int cb = wn + nt * 8 + tg * 2;
                if (r0 < M) *(float2*)(C + (size_t)r0 * HID + cb) =
                    make_float2(acc[mt][nt][0], acc[mt][nt][1]);
                if (r1 < M) *(float2*)(C + (size_t)r1 * HID + cb) =
                    make_float2(acc[mt][nt][2], acc[mt][nt][3]);
            }
        }
    }
}

// ------------------------- gemm_r: g_R = z @ W1a (runs on side stream, hidden under agg) -------------------------
__global__ __launch_bounds__(256, 2) void gemm_r_kernel(
    const float* __restrict__ z, const float* __restrict__ W1, int M)
{
    extern __shared__ uint32_t sm[];
    uint32_t* As = sm;                  // [128][PAF]
    uint32_t* Bs = sm + 128 * PAF;      // [64][PB]

    const int tid  = threadIdx.x;
    const int wid  = tid >> 5;
    const int lane = tid & 31;
    const int g    = lane >> 2;
    const int tg   = lane & 3;
    const int wm   = (wid & 3) << 5;
    const int wn   = (wid >> 2) << 6;
    const int rowBase = blockIdx.x * 128;

#pragma unroll
    for (int it = 0; it < 16; it++) {
        const int i = it * 256 + tid;
        const int row = i >> 5;
        const int c4  = (i & 31) << 2;
        const int gr = rowBase + row;
        float4 v = make_float4(0.f, 0.f, 0.f, 0.f);
        if (gr < M) v = *(const float4*)(z + (size_t)gr * HID + c4);
        uint32_t* p = As + row * PAF + c4;
        p[0] = f2tf(v.x); p[1] = f2tf(v.y); p[2] = f2tf(v.z); p[3] = f2tf(v.w);
    }

    float acc[2][8][4];
#pragma unroll
    for (int mt = 0; mt < 2; mt++)
#pragma unroll
        for (int nt = 0; nt < 8; nt++)
#pragma unroll
            for (int i = 0; i < 4; i++) acc[mt][nt][i] = 0.f;

    for (int chunk = 0; chunk < 2; chunk++) {
#pragma unroll
        for (int it = 0; it < 8; it++) {
            const int i = it * 256 + tid;
            const int k  = i >> 5;
            const int n4 = (i & 31) << 2;
            const float4 v = *(const float4*)(W1 + (size_t)(chunk * 64 + k) * HID + n4);
            uint32_t* p = Bs + k * PB + n4;
            p[0] = f2tf(v.x); p[1] = f2tf(v.y); p[2] = f2tf(v.z); p[3] = f2tf(v.w);
        }
        __syncthreads();
        mma_chunk(acc, As, PAF, chunk * 64, Bs, wm, wn, g, tg);
        __syncthreads();
    }

#pragma unroll
    for (int mt = 0; mt < 2; mt++) {
        const int r0 = rowBase + wm + mt * 16 + g;
        const int r1 = r0 + 8;
#pragma unroll
        for (int nt = 0; nt < 8; nt++) {
            const int cb = wn + nt * 8 + tg * 2;
            if (r0 < M) *(float2*)(g_R + (size_t)r0 * HID + cb) =
                make_float2(acc[mt][nt][0], acc[mt][nt][1]);
            if (r1 < M) *(float2*)(g_R + (size_t)r1 * HID + cb) =
                make_float2(acc[mt][nt][2], acc[mt][nt][3]);
        }
    }
}

// ------------------------- fused MLP: hidden = relu(R + agg@W1b + b1); out = hidden@W2 + b2 -------------------------
#define FUSED_SMEM (104448)

__global__ __launch_bounds__(256, 2) void fused_mlp_kernel(
    const float* __restrict__ W1, const float* __restrict__ b1,
    const float* __restrict__ W2, const float* __restrict__ b2,
    float* __restrict__ out, int M)
{
    extern __shared__ uint32_t sm[];
    uint32_t* As1 = sm;                 // [128][PAC]
    uint32_t* Bs1 = sm + 8704;          // [64][PB]
    uint32_t* hid = sm;                 // [128][PAF] (clobbers As1/Bs1)
    uint32_t* Bs2 = sm + 17408;         // [64][PB]

    const int tid  = threadIdx.x;
    const int wid  = tid >> 5;
    const int lane = tid & 31;
    const int g    = lane >> 2;
    const int tg   = lane & 3;
    const int wm   = (wid & 3) << 5;
    const int wn   = (wid >> 2) << 6;
    const int rowBase = blockIdx.x * 128;

    float acc[2][8][4];
#pragma unroll
    for (int mt = 0; mt < 2; mt++)
#pragma unroll
        for (int nt = 0; nt < 8; nt++)
#pragma unroll
            for (int i = 0; i < 4; i++) acc[mt][nt][i] = 0.f;

    // ---- stage 1: K=128 over agg with W1b (= W1 rows 128..255) ----
    const float* W1b = W1 + (size_t)128 * HID;
    for (int chunk = 0; chunk < 2; chunk++) {
        const int kloc = chunk * 64;
#pragma unroll
        for (int it = 0; it < 8; it++) {
            const int i = it * 256 + tid;
            const int row = i >> 4;
            const int c4  = (i & 15) << 2;
            const int gr = rowBase + row;
            float4 v = make_float4(0.f, 0.f, 0.f, 0.f);
            if (gr < M) v = *(const float4*)(g_agg + (size_t)gr * HID + kloc + c4);
            uint32_t* p = As1 + row * PAC + c4;
            p[0] = f2tf(v.x); p[1] = f2tf(v.y); p[2] = f2tf(v.z); p[3] = f2tf(v.w);
        }
#pragma unroll
        for (int it = 0; it < 8; it++) {
            const int i = it * 256 + tid;
            const int k  = i >> 5;
            const int n4 = (i & 31) << 2;
            const float4 v = *(const float4*)(W1b + (size_t)(kloc + k) * HID + n4);
            uint32_t* p = Bs1 + k * PB + n4;
            p[0] = f2tf(v.x); p[1] = f2tf(v.y); p[2] = f2tf(v.z); p[3] = f2tf(v.w);
        }
        __syncthreads();
        mma_chunk(acc, As1, PAC, 0, Bs1, wm, wn, g, tg);
        __syncthreads();
    }

    // ---- stage-1 epilogue: hid = tf32(relu(R + acc + b1)) ----
#pragma unroll
    for (int mt = 0; mt < 2; mt++) {
        const int lr0 = wm + mt * 16 + g;
        const int lr1 = lr0 + 8;
        const int r0 = rowBase + lr0;
        const int r1 = rowBase + lr1;
#pragma unroll
        for (int nt = 0; nt < 8; nt++) {
            const int cb = wn + nt * 8 + tg * 2;
            const float bb0 = b1[cb], bb1 = b1[cb + 1];
            float2 R0 = make_float2(0.f, 0.f), R1 = make_float2(0.f, 0.f);
            if (r0 < M) R0 = *(const float2*)(g_R + (size_t)r0 * HID + cb);
            if (r1 < M) R1 = *(const float2*)(g_R + (size_t)r1 * HID + cb);
            uint2 v0, v1;
            v0.x = f2tf(fmaxf(R0.x + acc[mt][nt][0] + bb0, 0.f));
            v0.y = f2tf(fmaxf(R0.y + acc[mt][nt][1] + bb1, 0.f));
            v1.x = f2tf(fmaxf(R1.x + acc[mt][nt][2] + bb0, 0.f));
            v1.y = f2tf(fmaxf(R1.y + acc[mt][nt][3] + bb1, 0.f));
            *(uint2*)(hid + lr0 * PAF + cb) = v0;
            *(uint2*)(hid + lr1 * PAF + cb) = v1;
        }
    }
    __syncthreads();

    // ---- stage 2: out = hid @ W2 + b2 ----
#pragma unroll
    for (int mt = 0; mt < 2; mt++)
#pragma unroll
        for (int nt = 0; nt < 8; nt++)
#pragma unroll
            for (int i = 0; i < 4; i++) acc[mt][nt][i] = 0.f;

    for (int chunk = 0; chunk < 2; chunk++) {
#pragma unroll
        for (int it = 0; it < 8; it++) {
            const int i = it * 256 + tid;
            const int k  = i >> 5;
            const int n4 = (i & 31) << 2;
            const float4 v = *(const float4*)(W2 + (size_t)(chunk * 64 + k) * HID + n4);
            uint32_t* p = Bs2 + k * PB + n4;
            p[0] = f2tf(v.x); p[1] = f2tf(v.y); p[2] = f2tf(v.z); p[3] = f2tf(v.w);
        }
        __syncthreads();
        mma_chunk(acc, hid, PAF, chunk * 64, Bs2, wm, wn, g, tg);
        __syncthreads();
    }

#pragma unroll
    for (int mt = 0; mt < 2; mt++) {
        const int r0 = rowBase + wm + mt * 16 + g;
        const int r1 = r0 + 8;
#pragma unroll
        for (int nt = 0; nt < 8; nt++) {
            const int cb = wn + nt * 8 + tg * 2;
            const float bb0 = b2[cb], bb1 = b2[cb + 1];
            if (r0 < M) *(float2*)(out + (size_t)r0 * HID + cb) =
                make_float2(acc[mt][nt][0] + bb0, acc[mt][nt][1] + bb1);
            if (r1 < M) *(float2*)(out + (size_t)r1 * HID + cb) =
                make_float2(acc[mt][nt][2] + bb0, acc[mt][nt][3] + bb1);
        }
    }
}

// ------------------------- CSR build -------------------------
__global__ void zero_deg_kernel(int nNodes)
{
    int i = blockIdx.x * blockDim.x + threadIdx.x;
    if (i < nNodes) g_deg[i] = 0;
}

__global__ void deg_kernel(const int* __restrict__ dst, int nE)
{
    int e = blockIdx.x * blockDim.x + threadIdx.x;
    if (e < nE) atomicAdd(&g_deg[dst[e]], 1);
}

__global__ __launch_bounds__(1024) void scan_kernel(int nNodes)
{
    __shared__ int warpPre[32];
    __shared__ int s_carry;
    const int tid = threadIdx.x;
    const int lane = tid & 31;
    const int wid = tid >> 5;
    if (tid == 0) s_carry = 0;
    __syncthreads();
    const int nChunks = (nNodes + 1023) >> 10;
    for (int c = 0; c < nChunks; c++) {
        const int i = (c << 10) + tid;
        const int v = (i < nNodes) ? g_deg[i] : 0;
        int incl = v;
#pragma unroll
        for (int o = 1; o < 32; o <<= 1) {
            int t = __shfl_up_sync(0xffffffffu, incl, o);
            if (lane >= o) incl += t;
        }
        if (lane == 31) warpPre[wid] = incl;
        __syncthreads();
        if (wid == 0) {
            int ws = warpPre[lane];
            int wincl = ws;
#pragma unroll
            for (int o = 1; o < 32; o <<= 1) {
                int t = __shfl_up_sync(0xffffffffu, wincl, o);
                if (lane >= o) wincl += t;
            }
            warpPre[lane] = wincl - ws;
        }
        __syncthreads();
        const int excl = s_carry + warpPre[wid] + incl - v;
        if (i < nNodes) { g_off[i] = excl; g_cur[i] = excl; }
        __syncthreads();
        if (tid == 1023) s_carry = excl + v;
        __syncthreads();
    }
    if (tid == 0) g_off[nNodes] = s_carry;
}

__global__ void scatter_kernel(const int* __restrict__ dst, int nE)
{
    int e = blockIdx.x * blockDim.x + threadIdx.x;
    if (e < nE) {
        int p = atomicAdd(&g_cur[dst[e]], 1);
        g_csr[p] = e;
    }
}

// ------------------------- per-node gather-max (edge loop unrolled 2x for MLP) -------------------------
__global__ __launch_bounds__(256) void agg_kernel(
    const int* __restrict__ src, const float* __restrict__ ew,
    const float* __restrict__ Wm, const float* __restrict__ bm,
    int nNodes)
{
    const int warpId = (blockIdx.x * blockDim.x + threadIdx.x) >> 5;
    const int lane = threadIdx.x & 31;
    if (warpId >= nNodes) return;
    const int n = warpId;
    const float4 ww4 = *(const float4*)(Wm + 256 * HID + lane * 4);
    const int s0 = g_off[n], s1 = g_off[n + 1];
    float4 m = make_float4(-FLT_MAX, -FLT_MAX, -FLT_MAX, -FLT_MAX);
    for (int base = s0; base < s1; base += 32) {
        const int idx = base + lane;
        int sv = 0; float wv = 0.f;
        if (idx < s1) {
            const int e = g_csr[idx];
            sv = src[e];
            wv = ew[e];
        }
        const int cnt = min(32, s1 - base);
        int j = 0;
        for (; j + 1 < cnt; j += 2) {
            const int   sj0 = __shfl_sync(0xffffffffu, sv, j);
            const float wj0 = __shfl_sync(0xffffffffu, wv, j);
            const int   sj1 = __shfl_sync(0xffffffffu, sv, j + 1);
            const float wj1 = __shfl_sync(0xffffffffu, wv, j + 1);
            const float4 b0 = *(const float4*)(g_B + (size_t)sj0 * HID + lane * 4);
            const float4 b1 = *(const float4*)(g_B + (size_t)sj1 * HID + lane * 4);
            m.x = fmaxf(m.x, fmaf(wj0, ww4.x, b0.x));
            m.y = fmaxf(m.y, fmaf(wj0, ww4.y, b0.y));
            m.z = fmaxf(m.z, fmaf(wj0, ww4.z, b0.z));
            m.w = fmaxf(m.w, fmaf(wj0, ww4.w, b0.w));
            m.x = fmaxf(m.x, fmaf(wj1, ww4.x, b1.x));
            m.y = fmaxf(m.y, fmaf(wj1, ww4.y, b1.y));
            m.z = fmaxf(m.z, fmaf(wj1, ww4.z, b1.z));
            m.w = fmaxf(m.w, fmaf(wj1, ww4.w, b1.w));
        }
        if (j < cnt) {
            const int   sj = __shfl_sync(0xffffffffu, sv, j);
            const float wj = __shfl_sync(0xffffffffu, wv, j);
            const float4 b4 = *(const float4*)(g_B + (size_t)sj * HID + lane * 4);
            m.x = fmaxf(m.x, fmaf(wj, ww4.x, b4.x));
            m.y = fmaxf(m.y, fmaf(wj, ww4.y, b4.y));
            m.z = fmaxf(m.z, fmaf(wj, ww4.z, b4.z));
            m.w = fmaxf(m.w, fmaf(wj, ww4.w, b4.w));
        }
    }
    float4 o;
    if (s1 > s0) {
        const float4 a4 = *(const float4*)(g_A + (size_t)n * HID + lane * 4);
        const float4 bm4 = *(const float4*)(bm + lane * 4);
        o = make_float4(a4.x + bm4.x + m.x, a4.y + bm4.y + m.y,
                        a4.z + bm4.z + m.z, a4.w + bm4.w + m.w);
    } else {
        o = make_float4(0.f, 0.f, 0.f, 0.f);
    }
    *(float4*)(g_agg + (size_t)n * HID + lane * 4) = o;
}

// ------------------------- launch -------------------------
extern "C" void kernel_launch(void* const* d_in, const int* in_sizes, int n_in,
                              void* d_out, int out_size)
{
    const float* z   = (const float*)d_in[0];
    const float* ew  = (const float*)d_in[1];
    const int*   esrc= (const int*)d_in[2];
    const int*   edst= (const int*)d_in[3];
    const float* Wm  = (const float*)d_in[4];
    const float* bm  = (const float*)d_in[5];
    const float* W1  = (const float*)d_in[6];
    const float* b1  = (const float*)d_in[7];
    const float* W2  = (const float*)d_in[8];
    const float* b2  = (const float*)d_in[9];
    float* out = (float*)d_out;

    const int nNodes = in_sizes[0] / HID;
    const int nEdges = in_sizes[1];

    cudaFuncSetAttribute(gemm2_kernel, cudaFuncAttributeMaxDynamicSharedMemorySize, GEMM2_SMEM);
    cudaFuncSetAttribute(gemm_r_kernel, cudaFuncAttributeMaxDynamicSharedMemorySize, GEMM2_SMEM);
    cudaFuncSetAttribute(fused_mlp_kernel, cudaFuncAttributeMaxDynamicSharedMemorySize, FUSED_SMEM);

    // lazily-created side stream + fork/join events (host-side objects, no device mem)
    static cudaStream_t s_side = nullptr;
    static cudaEvent_t  s_evFork = nullptr, s_evCsr = nullptr, s_evR = nullptr;
    if (!s_side) {
        cudaStreamCreateWithFlags(&s_side, cudaStreamNonBlocking);
        cudaEventCreateWithFlags(&s_evFork, cudaEventDisableTiming);
        cudaEventCreateWithFlags(&s_evCsr, cudaEventDisableTiming);
        cudaEventCreateWithFlags(&s_evR, cudaEventDisableTiming);
    }

    const int gemmGrid = (nNodes + 127) / 128;
    const int edgeGrid = (nEdges + 255) / 256;
    const int nodeGrid = (nNodes + 255) / 256;
    const int aggGrid  = (nNodes + 7) / 8;

    // fork
    cudaEventRecord(s_evFork, 0);
    cudaStreamWaitEvent(s_side, s_evFork, 0);

    // side stream: CSR build, then g_R = z@W1a (overlaps agg on main stream)
    zero_deg_kernel<<<nodeGrid, 256, 0, s_side>>>(nNodes);
    deg_kernel<<<edgeGrid, 256, 0, s_side>>>(edst, nEdges);
    scan_kernel<<<1, 1024, 0, s_side>>>(nNodes);
    scatter_kernel<<<edgeGrid, 256, 0, s_side>>>(edst, nEdges);
    cudaEventRecord(s_evCsr, s_side);
    gemm_r_kernel<<<gemmGrid, 256, GEMM2_SMEM, s_side>>>(z, W1, nNodes);
    cudaEventRecord(s_evR, s_side);

    // main stream: shared-A dual projection g_A = z@Wd, g_B = z@Ws
    gemm2_kernel<<<gemmGrid, 256, GEMM2_SMEM>>>(z, Wm, nNodes);

    // join CSR, then segment max (gather form); g_R gemm runs concurrently on side
    cudaStreamWaitEvent(0, s_evCsr, 0);
    agg_kernel<<<aggGrid, 256>>>(esrc, ew, Wm, bm, nNodes);

    // join g_R, then fused: hidden = relu(R + agg@W1b + b1); out = hidden@W2 + b2
    cudaStreamWaitEvent(0, s_evR, 0);
    fused_mlp_kernel<<<gemmGrid, 256, FUSED_SMEM>>>(W1, b1, W2, b2, out, nNodes);
}